// round 5
// baseline (speedup 1.0000x reference)
#include <cuda_runtime.h>

// ---------------------------------------------------------------------------
// 2-layer GCN: h1 = relu(Â (x W1) + b1); out = log_softmax(Â (h1 W2) + b2)
// with Â = D^-1/2 (A+I) D^-1/2.  Normalization factored as pre/post dinv scale.
// n = 100000 nodes (feat 2 -> 16 -> 2), E = 3.2M directed edges.
// edge_index dtype auto-detected (JAX default x64-disabled -> int32).
// ---------------------------------------------------------------------------

#define N_MAX 100000
#define F1 16

// Scratch (no allocation allowed -> __device__ globals)
__device__ float g_deg [N_MAX];
__device__ float g_dinv[N_MAX];
__device__ float g_h1s [N_MAX * F1];   // dinv[i] * (x[i] @ W1)
__device__ float g_acc1[N_MAX * F1];   // edge-sum accumulator, layer 1
__device__ float g_h2s [N_MAX * 2];    // dinv[i] * (relu1[i] @ W2)
__device__ float g_acc2[N_MAX * 2];    // edge-sum accumulator, layer 2
__device__ int   g_is64;               // 1 if edge_index is int64

// Kd: dtype probe. If data were int64 (values < 1e5), every odd 32-bit word
// (the high half) is zero. For int32 data those words are random indices.
__global__ void k_detect(const unsigned int* __restrict__ w, int nwords) {
    __shared__ int nz;
    if (threadIdx.x == 0) nz = 0;
    __syncthreads();
    for (int i = threadIdx.x; i < 4096; i += blockDim.x) {
        int idx = 2 * i + 1;
        if (idx < nwords && w[idx] != 0u) nz = 1;
    }
    __syncthreads();
    if (threadIdx.x == 0) g_is64 = (nz == 0);
}

__device__ __forceinline__ int edge_idx(const void* ei, long long pos) {
    if (g_is64) return (int)((const long long*)ei)[pos];
    return ((const int*)ei)[pos];
}

// K0: deg = 1 (self loop), zero accumulators
__global__ void k_init(int n) {
    int i = blockIdx.x * blockDim.x + threadIdx.x;
    if (i >= n) return;
    g_deg[i] = 1.0f;
    float4 z = make_float4(0.f, 0.f, 0.f, 0.f);
    float4* a = reinterpret_cast<float4*>(g_acc1 + i * F1);
    a[0] = z; a[1] = z; a[2] = z; a[3] = z;
    reinterpret_cast<float2*>(g_acc2)[i] = make_float2(0.f, 0.f);
}

// K1: degree count at target nodes
__global__ void k_deg(const void* __restrict__ ei, int E) {
    int e = blockIdx.x * blockDim.x + threadIdx.x;
    if (e >= E) return;
    int d = edge_idx(ei, (long long)E + e);
    atomicAdd(&g_deg[d], 1.0f);
}

// K2: dinv + pre-scaled layer-1 features  h1s[i] = dinv[i] * (x[i] @ W1)
__global__ void k_l1_pre(const float* __restrict__ x,
                         const float* __restrict__ W1, int n) {
    __shared__ float w[32];                 // W1 is [2,16] row-major
    if (threadIdx.x < 32) w[threadIdx.x] = W1[threadIdx.x];
    __syncthreads();
    int i = blockIdx.x * blockDim.x + threadIdx.x;
    if (i >= n) return;
    float di = rsqrtf(g_deg[i]);            // deg >= 1 always (self loop)
    g_dinv[i] = di;
    float2 xv = reinterpret_cast<const float2*>(x)[i];
    float* h = g_h1s + i * F1;
#pragma unroll
    for (int j = 0; j < F1; j++)
        h[j] = di * (xv.x * w[j] + xv.y * w[F1 + j]);
}

// K3: layer-1 edge scatter: acc1[dst] += h1s[src]  (vector float4 REDs)
__global__ void k_scat1(const void* __restrict__ ei, int E) {
    int e = blockIdx.x * blockDim.x + threadIdx.x;
    if (e >= E) return;
    int s = edge_idx(ei, e);
    int d = edge_idx(ei, (long long)E + e);
    const float4* hs = reinterpret_cast<const float4*>(g_h1s + s * F1);
    float4* a = reinterpret_cast<float4*>(g_acc1 + d * F1);
    float4 v0 = hs[0], v1 = hs[1], v2 = hs[2], v3 = hs[3];
    atomicAdd(&a[0], v0);
    atomicAdd(&a[1], v1);
    atomicAdd(&a[2], v2);
    atomicAdd(&a[3], v3);
}

// K4: finalize layer 1 (post-scale + bias + relu), then layer-2 pre-scale
__global__ void k_l1_fin(const float* __restrict__ b1,
                         const float* __restrict__ W2, int n) {
    __shared__ float w[32];                 // W2 is [16,2] row-major
    __shared__ float bb[F1];
    if (threadIdx.x < 32) w[threadIdx.x] = W2[threadIdx.x];
    if (threadIdx.x < F1) bb[threadIdx.x] = b1[threadIdx.x];
    __syncthreads();
    int i = blockIdx.x * blockDim.x + threadIdx.x;
    if (i >= n) return;
    float di = g_dinv[i];
    const float* ac = g_acc1 + i * F1;
    const float* hs = g_h1s + i * F1;
    float o0 = 0.f, o1 = 0.f;
#pragma unroll
    for (int j = 0; j < F1; j++) {
        // self-loop term: dinv[i]*h[i] == h1s[i]
        float r = fmaxf(di * (ac[j] + hs[j]) + bb[j], 0.f);
        o0 += r * w[j * 2 + 0];
        o1 += r * w[j * 2 + 1];
    }
    reinterpret_cast<float2*>(g_h2s)[i] = make_float2(di * o0, di * o1);
}

// K5: layer-2 edge scatter: acc2[dst] += h2s[src] (float2 RED)
__global__ void k_scat2(const void* __restrict__ ei, int E) {
    int e = blockIdx.x * blockDim.x + threadIdx.x;
    if (e >= E) return;
    int s = edge_idx(ei, e);
    int d = edge_idx(ei, (long long)E + e);
    float2 v = reinterpret_cast<const float2*>(g_h2s)[s];
    atomicAdd(&reinterpret_cast<float2*>(g_acc2)[d], v);
}

// K6: finalize layer 2 + log_softmax over 2 classes
__global__ void k_l2_fin(const float* __restrict__ b2,
                         float* __restrict__ out, int n) {
    int i = blockIdx.x * blockDim.x + threadIdx.x;
    if (i >= n) return;
    float di = g_dinv[i];
    float2 a = reinterpret_cast<const float2*>(g_acc2)[i];
    float2 h = reinterpret_cast<const float2*>(g_h2s)[i];
    float o0 = di * (a.x + h.x) + b2[0];
    float o1 = di * (a.y + h.y) + b2[1];
    float m = fmaxf(o0, o1);
    float lse = m + logf(expf(o0 - m) + expf(o1 - m));
    reinterpret_cast<float2*>(out)[i] = make_float2(o0 - lse, o1 - lse);
}

extern "C" void kernel_launch(void* const* d_in, const int* in_sizes, int n_in,
                              void* d_out, int out_size) {
    const float* x  = (const float*)d_in[0];
    const void*  ei = d_in[1];
    const float* W1 = (const float*)d_in[2];
    const float* b1 = (const float*)d_in[3];
    const float* W2 = (const float*)d_in[4];
    const float* b2 = (const float*)d_in[5];
    float*       out = (float*)d_out;

    int n = in_sizes[0] / 2;        // [n, 2] features
    int E = in_sizes[1] / 2;        // [2, E] edge index

    const int TB = 256;
    int gn = (n + TB - 1) / TB;
    int ge = (E + TB - 1) / TB;

    // in_sizes[1] elements; as 32-bit words that's at least in_sizes[1] words
    k_detect<<<1, 256>>>((const unsigned int*)ei, in_sizes[1]);
    k_init  <<<gn, TB>>>(n);
    k_deg   <<<ge, TB>>>(ei, E);
    k_l1_pre<<<gn, TB>>>(x, W1, n);
    k_scat1 <<<ge, TB>>>(ei, E);
    k_l1_fin<<<gn, TB>>>(b1, W2, n);
    k_scat2 <<<ge, TB>>>(ei, E);
    k_l2_fin<<<gn, TB>>>(b2, out, n);
}

// round 6
// speedup vs baseline: 1.7834x; 1.7834x over previous
#include <cuda_runtime.h>

// ---------------------------------------------------------------------------
// 2-layer GCN, normalization factored: out_agg[d] = dinv[d]*(Σ_e dinv[s]v[s] + dinv[d]v[d])
// Key optimization: Â(xW1) = (Âx)W1  -> aggregate the 2-dim features, project after.
// Both scatter layers move only 8B gather + 8B float2-RED per edge.
// ---------------------------------------------------------------------------

#define N_MAX 100000
#define F1 16

__device__ float2 g_xs  [N_MAX];   // dinv[i] * x[i]
__device__ float2 g_acc1[N_MAX];   // layer-1 edge sum (2-dim space)
__device__ float2 g_h2s [N_MAX];   // dinv[i] * (relu(l1) @ W2)
__device__ float2 g_acc2[N_MAX];   // layer-2 edge sum
__device__ float  g_deg [N_MAX];
__device__ float  g_dinv[N_MAX];
__device__ int    g_is64;          // 1 if edge_index is int64

// dtype probe: int64 indices < 1e5 -> every odd 32-bit word is 0.
__global__ void k_detect(const unsigned int* __restrict__ w, int nwords) {
    __shared__ int nz;
    if (threadIdx.x == 0) nz = 0;
    __syncthreads();
    for (int i = threadIdx.x; i < 4096; i += blockDim.x) {
        int idx = 2 * i + 1;
        if (idx < nwords && w[idx] != 0u) nz = 1;
    }
    __syncthreads();
    if (threadIdx.x == 0) g_is64 = (nz == 0);
}

__global__ void k_init(int n) {
    int i = blockIdx.x * blockDim.x + threadIdx.x;
    if (i >= n) return;
    g_deg[i] = 1.0f;                       // self loop
    float2 z = make_float2(0.f, 0.f);
    g_acc1[i] = z;
    g_acc2[i] = z;
}

// degree count at targets, 4 edges/thread via int4
__global__ void k_deg(const void* __restrict__ ei, int E) {
    int t = blockIdx.x * blockDim.x + threadIdx.x;
    int base = t * 4;
    if (base >= E) return;
    if (!g_is64) {
        const int* dst = (const int*)ei + E;
        if (base + 4 <= E) {
            int4 d = *reinterpret_cast<const int4*>(dst + base);
            atomicAdd(&g_deg[d.x], 1.0f);
            atomicAdd(&g_deg[d.y], 1.0f);
            atomicAdd(&g_deg[d.z], 1.0f);
            atomicAdd(&g_deg[d.w], 1.0f);
        } else {
            for (int e = base; e < E; e++) atomicAdd(&g_deg[dst[e]], 1.0f);
        }
    } else {
        const long long* dst = (const long long*)ei + E;
        int end = min(base + 4, E);
        for (int e = base; e < end; e++) atomicAdd(&g_deg[(int)dst[e]], 1.0f);
    }
}

// dinv + pre-scaled features
__global__ void k_pre(const float* __restrict__ x, int n) {
    int i = blockIdx.x * blockDim.x + threadIdx.x;
    if (i >= n) return;
    float di = rsqrtf(g_deg[i]);
    g_dinv[i] = di;
    float2 xv = reinterpret_cast<const float2*>(x)[i];
    g_xs[i] = make_float2(di * xv.x, di * xv.y);
}

// generic 2-dim scatter: acc[dst] += val[src], 4 edges/thread
__device__ __forceinline__ void scat2d(const void* ei, int E,
                                       const float2* __restrict__ val,
                                       float2* __restrict__ acc) {
    int t = blockIdx.x * blockDim.x + threadIdx.x;
    int base = t * 4;
    if (base >= E) return;
    if (!g_is64) {
        const int* sp = (const int*)ei;
        const int* dp = sp + E;
        if (base + 4 <= E) {
            int4 s = *reinterpret_cast<const int4*>(sp + base);
            int4 d = *reinterpret_cast<const int4*>(dp + base);
            float2 v0 = val[s.x], v1 = val[s.y], v2 = val[s.z], v3 = val[s.w];
            atomicAdd(&acc[d.x], v0);
            atomicAdd(&acc[d.y], v1);
            atomicAdd(&acc[d.z], v2);
            atomicAdd(&acc[d.w], v3);
        } else {
            for (int e = base; e < E; e++) atomicAdd(&acc[dp[e]], val[sp[e]]);
        }
    } else {
        const long long* sp = (const long long*)ei;
        const long long* dp = sp + E;
        int end = min(base + 4, E);
        for (int e = base; e < end; e++)
            atomicAdd(&acc[(int)dp[e]], val[(int)sp[e]]);
    }
}

__global__ void k_scat1(const void* __restrict__ ei, int E) {
    scat2d(ei, E, g_xs, g_acc1);
}
__global__ void k_scat2(const void* __restrict__ ei, int E) {
    scat2d(ei, E, g_h2s, g_acc2);
}

// finalize layer 1: project aggregated 2-dim -> 16 -> relu -> @W2 -> pre-scale
__global__ void k_fin1(const float* __restrict__ W1,
                       const float* __restrict__ b1,
                       const float* __restrict__ W2, int n) {
    __shared__ float w1[32];   // [2,16] row-major
    __shared__ float w2[32];   // [16,2] row-major
    __shared__ float bb[F1];
    if (threadIdx.x < 32) { w1[threadIdx.x] = W1[threadIdx.x];
                            w2[threadIdx.x] = W2[threadIdx.x]; }
    if (threadIdx.x < F1)   bb[threadIdx.x] = b1[threadIdx.x];
    __syncthreads();
    int i = blockIdx.x * blockDim.x + threadIdx.x;
    if (i >= n) return;
    float di = g_dinv[i];
    float2 a  = g_acc1[i];
    float2 xs = g_xs[i];
    float t0 = di * (a.x + xs.x);   // aggregated feature 0
    float t1 = di * (a.y + xs.y);   // aggregated feature 1
    float o0 = 0.f, o1 = 0.f;
#pragma unroll
    for (int j = 0; j < F1; j++) {
        float r = fmaxf(t0 * w1[j] + t1 * w1[F1 + j] + bb[j], 0.f);
        o0 += r * w2[2 * j];
        o1 += r * w2[2 * j + 1];
    }
    g_h2s[i] = make_float2(di * o0, di * o1);
}

// finalize layer 2 + log_softmax
__global__ void k_fin2(const float* __restrict__ b2,
                       float* __restrict__ out, int n) {
    int i = blockIdx.x * blockDim.x + threadIdx.x;
    if (i >= n) return;
    float di = g_dinv[i];
    float2 a = g_acc2[i];
    float2 h = g_h2s[i];
    float o0 = di * (a.x + h.x) + b2[0];
    float o1 = di * (a.y + h.y) + b2[1];
    float m = fmaxf(o0, o1);
    float lse = m + logf(expf(o0 - m) + expf(o1 - m));
    reinterpret_cast<float2*>(out)[i] = make_float2(o0 - lse, o1 - lse);
}

extern "C" void kernel_launch(void* const* d_in, const int* in_sizes, int n_in,
                              void* d_out, int out_size) {
    const float* x  = (const float*)d_in[0];
    const void*  ei = d_in[1];
    const float* W1 = (const float*)d_in[2];
    const float* b1 = (const float*)d_in[3];
    const float* W2 = (const float*)d_in[4];
    const float* b2 = (const float*)d_in[5];
    float*       out = (float*)d_out;

    int n = in_sizes[0] / 2;        // [n, 2]
    int E = in_sizes[1] / 2;        // [2, E]

    const int TB = 256;
    int gn  = (n + TB - 1) / TB;
    int ge4 = (E / 4 + TB) / TB + 1;   // 4 edges per thread (slight over-provision)

    k_detect<<<1, 256>>>((const unsigned int*)ei, in_sizes[1]);
    k_init  <<<gn, TB>>>(n);
    k_deg   <<<ge4, TB>>>(ei, E);
    k_pre   <<<gn, TB>>>(x, n);
    k_scat1 <<<ge4, TB>>>(ei, E);
    k_fin1  <<<gn, TB>>>(W1, b1, W2, n);
    k_scat2 <<<ge4, TB>>>(ei, E);
    k_fin2  <<<gn, TB>>>(b2, out, n);
}